// round 7
// baseline (speedup 1.0000x reference)
#include <cuda_runtime.h>
#include <cstdint>

// GeneWiseDecoder: out[b,g] = (gelu(gelu(x@W1[g]+b1[g]) @ W2[g] + b2[g])) @ W3[g] + b3[g]
// B=128, LATENT=128, HID=512, GENES=1000. All fp32 in/out.
// Strategy: TF32 mma.sync GEMMs with fp32 accumulation. 2000 CTAs: gene = bx>>1,
// batch-half (64 rows) = bx&1. h1 kept in SMEM as tf32. W tiles streamed with
// register-prefetch double buffering. Final W3 dot in full fp32.

static constexpr int GENES = 1000;
static constexpr int HID   = 512;
static constexpr int LAT   = 128;

// SMEM pitches (floats), padded for conflict-free fragment access
static constexpr int PH = 516;   // h1 [64][516]
static constexpr int PW = 260;   // W tile [32][260]
static constexpr int PX = 132;   // x  [64][132]

static constexpr int OFF_H1 = 0;                    // 64*516 = 33024
static constexpr int OFF_W  = OFF_H1 + 64 * PH;     // 33024
static constexpr int OFF_X  = OFF_W  + 32 * PW;     // +8320 = 41344
static constexpr int OFF_B1 = OFF_X  + 64 * PX;     // +8448 = 49792
static constexpr int OFF_B2 = OFF_B1 + 512;         // 50304
static constexpr int OFF_W3 = OFF_B2 + 512;         // 50816
static constexpr int OFF_O  = OFF_W3 + 512;         // 51328
static constexpr int SMEM_FLOATS = OFF_O + 64;      // 51392
static constexpr int SMEM_BYTES  = SMEM_FLOATS * 4; // 205568 B (< 227KB)

__device__ __forceinline__ float to_tf32(float v) {
    uint32_t u;
    asm("cvt.rna.tf32.f32 %0, %1;" : "=r"(u) : "f"(v));
    return __uint_as_float(u);
}

__device__ __forceinline__ float gelu_exact(float v) {
    // jax.nn.gelu(approximate=False) == x * Phi(x)
    return v * normcdff(v);
}

__device__ __forceinline__ void mma_tf32(float d[4], const uint32_t a[4],
                                         uint32_t b0, uint32_t b1) {
    asm volatile(
        "mma.sync.aligned.m16n8k8.row.col.f32.tf32.tf32.f32 "
        "{%0,%1,%2,%3},{%4,%5,%6,%7},{%8,%9},{%0,%1,%2,%3};"
        : "+f"(d[0]), "+f"(d[1]), "+f"(d[2]), "+f"(d[3])
        : "r"(a[0]), "r"(a[1]), "r"(a[2]), "r"(a[3]), "r"(b0), "r"(b1));
}

// Load one 32(K) x 256(N) fp32 tile into registers (ldb = 512 for both W1, W2)
__device__ __forceinline__ void load_tile(float4 pre[8], const float* __restrict__ gB,
                                          int k0, int n0, int tid) {
#pragma unroll
    for (int i = 0; i < 8; ++i) {
        int idx = tid + i * 256;
        int r = idx >> 6;        // 64 float4 per row
        int c = idx & 63;
        pre[i] = *reinterpret_cast<const float4*>(gB + (size_t)(k0 + r) * 512 + n0 + c * 4);
    }
}

// Store register tile to SMEM with RNA round-to-tf32
__device__ __forceinline__ void store_tile(float* __restrict__ shW, const float4 pre[8],
                                           int tid) {
#pragma unroll
    for (int i = 0; i < 8; ++i) {
        int idx = tid + i * 256;
        int r = idx >> 6;
        int c = idx & 63;
        float4 t;
        t.x = to_tf32(pre[i].x);
        t.y = to_tf32(pre[i].y);
        t.z = to_tf32(pre[i].z);
        t.w = to_tf32(pre[i].w);
        *reinterpret_cast<float4*>(shW + r * PW + c * 4) = t;
    }
}

// One K-chunk (32) of mma: CTA tile 64x256, warp tile 32x64, warp grid 2(m) x 4(n)
__device__ __forceinline__ void mma_chunk(float acc[2][8][4],
                                          const float* __restrict__ shA, int pa, int kBase,
                                          const float* __restrict__ shW,
                                          int wm, int wn, int grp, int qt) {
    const uint32_t* A = reinterpret_cast<const uint32_t*>(shA);
    const uint32_t* B = reinterpret_cast<const uint32_t*>(shW);
#pragma unroll
    for (int k8 = 0; k8 < 4; ++k8) {
        int cA = kBase + k8 * 8 + qt;
        uint32_t a[2][4];
#pragma unroll
        for (int mf = 0; mf < 2; ++mf) {
            int r = wm * 32 + mf * 16 + grp;
            a[mf][0] = A[r * pa + cA];
            a[mf][1] = A[(r + 8) * pa + cA];
            a[mf][2] = A[r * pa + cA + 4];
            a[mf][3] = A[(r + 8) * pa + cA + 4];
        }
        int kl = k8 * 8;
#pragma unroll
        for (int nf = 0; nf < 8; ++nf) {
            int cb = wn * 64 + nf * 8 + grp;
            uint32_t b0 = B[(kl + qt) * PW + cb];
            uint32_t b1 = B[(kl + 4 + qt) * PW + cb];
            mma_tf32(acc[0][nf], a[0], b0, b1);
            mma_tf32(acc[1][nf], a[1], b0, b1);
        }
    }
}

__global__ void __launch_bounds__(256, 1)
gene_mlp_kernel(const float* __restrict__ x,
                const float* __restrict__ W1, const float* __restrict__ b1,
                const float* __restrict__ W2, const float* __restrict__ b2,
                const float* __restrict__ W3, const float* __restrict__ b3,
                float* __restrict__ out) {
    extern __shared__ float sm[];
    float* shH  = sm + OFF_H1;
    float* shW  = sm + OFF_W;
    float* shX  = sm + OFF_X;
    float* shB1 = sm + OFF_B1;
    float* shB2 = sm + OFF_B2;
    float* shW3 = sm + OFF_W3;
    float* shO  = sm + OFF_O;

    const int g       = blockIdx.x >> 1;
    const int rowbase = (blockIdx.x & 1) * 64;
    const int tid  = threadIdx.x;
    const int lane = tid & 31;
    const int warp = tid >> 5;
    const int wm = warp & 1;    // 2 m-warps (32 rows each)
    const int wn = warp >> 1;   // 4 n-warps (64 cols each)
    const int grp = lane >> 2;
    const int qt  = lane & 3;

    // ---- stage x (as tf32), biases, W3; zero output accumulator ----
    for (int i = tid; i < 64 * 32; i += 256) {     // 64 rows x 32 float4
        int r = i >> 5, c = i & 31;
        float4 v = *reinterpret_cast<const float4*>(x + (size_t)(rowbase + r) * LAT + c * 4);
        float4 t;
        t.x = to_tf32(v.x); t.y = to_tf32(v.y); t.z = to_tf32(v.z); t.w = to_tf32(v.w);
        *reinterpret_cast<float4*>(shX + r * PX + c * 4) = t;
    }
    {
        const float* b1g = b1 + (size_t)g * HID;
        const float* b2g = b2 + (size_t)g * HID;
        const float* w3g = W3 + (size_t)g * HID;
        for (int i = tid; i < HID; i += 256) {
            shB1[i] = b1g[i];
            shB2[i] = b2g[i];
            shW3[i] = w3g[i];
        }
    }
    if (tid < 64) shO[tid] = 0.0f;

    // ================= Phase 1: h1 = gelu(x @ W1 + b1), store tf32 in SMEM ======
    const float* W1g = W1 + (size_t)g * LAT * HID;
#pragma unroll 1
    for (int n1t = 0; n1t < 2; ++n1t) {
        const int n0 = n1t * 256;
        float acc[2][8][4];
#pragma unroll
        for (int mf = 0; mf < 2; ++mf)
#pragma unroll
            for (int nf = 0; nf < 8; ++nf)
#pragma unroll
                for (int i = 0; i < 4; ++i) acc[mf][nf][i] = 0.0f;

        float4 pre[8];
        load_tile(pre, W1g, 0, n0, tid);
#pragma unroll 1
        for (int kc = 0; kc < 4; ++kc) {
            __syncthreads();               // prior readers of shW done
            store_tile(shW, pre, tid);
            if (kc < 3) load_tile(pre, W1g, (kc + 1) * 32, n0, tid);
            __syncthreads();               // tile visible
            mma_chunk(acc, shX, PX, kc * 32, shW, wm, wn, grp, qt);
        }
        // epilogue: bias + gelu + tf32-store into shH
#pragma unroll
        for (int mf = 0; mf < 2; ++mf)
#pragma unroll
            for (int nf = 0; nf < 8; ++nf)
#pragma unroll
                for (int i = 0; i < 4; ++i) {
                    int row  = wm * 32 + mf * 16 + (i >> 1) * 8 + grp;
                    int colL = wn * 64 + nf * 8 + 2 * qt + (i & 1);
                    float v = acc[mf][nf][i] + shB1[n0 + colL];
                    shH[row * PH + n0 + colL] = to_tf32(gelu_exact(v));
                }
    }

    // ================= Phase 2: h2 = gelu(h1 @ W2 + b2); out += h2 . W3 =========
    const float* W2g = W2 + (size_t)g * HID * HID;
#pragma unroll 1
    for (int n2t = 0; n2t < 2; ++n2t) {
        const int n0 = n2t * 256;
        float acc[2][8][4];
#pragma unroll
        for (int mf = 0; mf < 2; ++mf)
#pragma unroll
            for (int nf = 0; nf < 8; ++nf)
#pragma unroll
                for (int i = 0; i < 4; ++i) acc[mf][nf][i] = 0.0f;

        float4 pre[8];
        load_tile(pre, W2g, 0, n0, tid);
#pragma unroll 1
        for (int kc = 0; kc < 16; ++kc) {
            __syncthreads();
            store_tile(shW, pre, tid);
            if (kc < 15) load_tile(pre, W2g, (kc + 1) * 32, n0, tid);
            __syncthreads();
            mma_chunk(acc, shH, PH, kc * 32, shW, wm, wn, grp, qt);
        }
        // epilogue: bias + gelu + fused dot with W3 (full fp32)
        float part[4] = {0.f, 0.f, 0.f, 0.f};
#pragma unroll
        for (int mf = 0; mf < 2; ++mf)
#pragma unroll
            for (int nf = 0; nf < 8; ++nf)
#pragma unroll
                for (int i = 0; i < 4; ++i) {
                    int col = n0 + wn * 64 + nf * 8 + 2 * qt + (i & 1);
                    float v = gelu_exact(acc[mf][nf][i] + shB2[col]);
                    part[mf * 2 + (i >> 1)] += v * shW3[col];
                }
        // reduce across the 4 lanes of each quad (they share rows)
#pragma unroll
        for (int r = 0; r < 4; ++r) {
            part[r] += __shfl_xor_sync(0xffffffffu, part[r], 1);
            part[r] += __shfl_xor_sync(0xffffffffu, part[r], 2);
        }
        if (qt == 0) {
#pragma unroll
            for (int r = 0; r < 4; ++r) {
                int row = wm * 32 + (r >> 1) * 16 + (r & 1) * 8 + grp;
                atomicAdd(&shO[row], part[r]);
            }
        }
    }

    __syncthreads();
    if (tid < 64) {
        out[(size_t)(rowbase + tid) * GENES + g] = shO[tid] + b3[g];
    }
}

extern "C" void kernel_launch(void* const* d_in, const int* in_sizes, int n_in,
                              void* d_out, int out_size) {
    const float* x  = (const float*)d_in[0];
    const float* W1 = (const float*)d_in[1];
    const float* b1 = (const float*)d_in[2];
    const float* W2 = (const float*)d_in[3];
    const float* b2 = (const float*)d_in[4];
    const float* W3 = (const float*)d_in[5];
    const float* b3 = (const float*)d_in[6];
    float* out = (float*)d_out;

    cudaFuncSetAttribute(gene_mlp_kernel,
                         cudaFuncAttributeMaxDynamicSharedMemorySize, SMEM_BYTES);
    gene_mlp_kernel<<<2 * GENES, 256, SMEM_BYTES>>>(x, W1, b1, W2, b2, W3, b3, out);
}

// round 8
// speedup vs baseline: 1.5068x; 1.5068x over previous
#include <cuda_runtime.h>
#include <cstdint>

// GeneWiseDecoder: out[b,g] = gelu(gelu(x@W1[g]+b1) @ W2[g] + b2) @ W3[g] + b3
// B=128, LATENT=128, HID=512, GENES=1000, fp32.
// TF32 mma.sync (RNA-rounded operands, fp32 accum). 2000 CTAs: gene=bx>>1,
// 64-row batch half = bx&1. 512 threads (16 warps, warp tile 16x64).
// W tiles double-buffered in SMEM, 1 __syncthreads per K-chunk.

static constexpr int GENES = 1000;
static constexpr int HID   = 512;
static constexpr int LAT   = 128;

static constexpr int PH = 516;            // h1 pitch (516 % 32 == 4 -> conflict-free A frags)
static constexpr int PW = 264;            // W pitch  (264 % 32 == 8 -> conflict-free B frags)
static constexpr int WCHUNK = 32 * PW;    // floats per W buffer

static constexpr int OFF_H  = 0;                      // 64*516 = 33024 floats
static constexpr int OFF_W  = 64 * PH;                // 2 buffers: 16896 floats
static constexpr int OFF_B1 = OFF_W + 2 * WCHUNK;     // 49920
static constexpr int OFF_B2 = OFF_B1 + 512;
static constexpr int OFF_W3 = OFF_B2 + 512;
static constexpr int OFF_O  = OFF_W3 + 512;
static constexpr int SMEM_FLOATS = OFF_O + 64;        // 51520
static constexpr int SMEM_BYTES  = SMEM_FLOATS * 4;   // 206080 B

__device__ __forceinline__ float to_tf32(float v) {
    uint32_t u;
    asm("cvt.rna.tf32.f32 %0, %1;" : "=r"(u) : "f"(v));
    return __uint_as_float(u);
}

__device__ __forceinline__ uint32_t ld_tf32(const float* __restrict__ p) {
    uint32_t u;
    asm("cvt.rna.tf32.f32 %0, %1;" : "=r"(u) : "f"(*p));
    return u;
}

__device__ __forceinline__ float gelu_exact(float v) {
    return v * normcdff(v);   // jax.nn.gelu(approximate=False)
}

__device__ __forceinline__ void mma_tf32(float d[4], const uint32_t a[4],
                                         uint32_t b0, uint32_t b1) {
    asm volatile(
        "mma.sync.aligned.m16n8k8.row.col.f32.tf32.tf32.f32 "
        "{%0,%1,%2,%3},{%4,%5,%6,%7},{%8,%9},{%0,%1,%2,%3};"
        : "+f"(d[0]), "+f"(d[1]), "+f"(d[2]), "+f"(d[3])
        : "r"(a[0]), "r"(a[1]), "r"(a[2]), "r"(a[3]), "r"(b0), "r"(b1));
}

// Load one 32(K) x 256(N) fp32 tile (ldb = 512) into 4 float4 regs per thread.
__device__ __forceinline__ void load_tile(float4 pre[4], const float* __restrict__ gB,
                                          int k0, int n0, int tid) {
#pragma unroll
    for (int i = 0; i < 4; ++i) {
        int idx = tid + i * 512;
        int r = idx >> 6;        // 64 float4 per row
        int c = idx & 63;
        pre[i] = *reinterpret_cast<const float4*>(gB + (size_t)(k0 + r) * 512 + n0 + c * 4);
    }
}

// Store register tile to a W SMEM buffer with RNA tf32 rounding.
__device__ __forceinline__ void store_tile(float* __restrict__ shW, const float4 pre[4],
                                           int tid) {
#pragma unroll
    for (int i = 0; i < 4; ++i) {
        int idx = tid + i * 512;
        int r = idx >> 6;
        int c = idx & 63;
        float4 t;
        t.x = to_tf32(pre[i].x);
        t.y = to_tf32(pre[i].y);
        t.z = to_tf32(pre[i].z);
        t.w = to_tf32(pre[i].w);
        *reinterpret_cast<float4*>(shW + r * PW + c * 4) = t;
    }
}

// One K=32 chunk of mma, A from SMEM (tf32, pitch pa). Warp tile 16x64.
__device__ __forceinline__ void mma_chunk_sh(float acc[8][4],
                                             const float* __restrict__ shA, int pa, int kBase,
                                             const float* __restrict__ shW,
                                             int wm, int wn, int grp, int qt) {
    const uint32_t* A = reinterpret_cast<const uint32_t*>(shA);
    const uint32_t* B = reinterpret_cast<const uint32_t*>(shW);
    const int r0 = wm * 16 + grp;
#pragma unroll
    for (int k8 = 0; k8 < 4; ++k8) {
        int cA = kBase + k8 * 8 + qt;
        uint32_t a[4];
        a[0] = A[r0 * pa + cA];
        a[1] = A[(r0 + 8) * pa + cA];
        a[2] = A[r0 * pa + cA + 4];
        a[3] = A[(r0 + 8) * pa + cA + 4];
        int kl = k8 * 8;
#pragma unroll
        for (int nf = 0; nf < 8; ++nf) {
            int cb = wn * 64 + nf * 8 + grp;
            uint32_t b0 = B[(kl + qt) * PW + cb];
            uint32_t b1 = B[(kl + 4 + qt) * PW + cb];
            mma_tf32(acc[nf], a, b0, b1);
        }
    }
}

// One K=32 chunk of mma, A straight from global x (fp32 -> tf32 cvt at load).
__device__ __forceinline__ void mma_chunk_gx(float acc[8][4],
                                             const float* __restrict__ xg, int kBase,
                                             const float* __restrict__ shW,
                                             int wm, int wn, int grp, int qt) {
    const uint32_t* B = reinterpret_cast<const uint32_t*>(shW);
    const int r0 = wm * 16 + grp;
#pragma unroll
    for (int k8 = 0; k8 < 4; ++k8) {
        int cA = kBase + k8 * 8 + qt;
        uint32_t a[4];
        a[0] = ld_tf32(xg + (size_t)r0 * LAT + cA);
        a[1] = ld_tf32(xg + (size_t)(r0 + 8) * LAT + cA);
        a[2] = ld_tf32(xg + (size_t)r0 * LAT + cA + 4);
        a[3] = ld_tf32(xg + (size_t)(r0 + 8) * LAT + cA + 4);
        int kl = k8 * 8;
#pragma unroll
        for (int nf = 0; nf < 8; ++nf) {
            int cb = wn * 64 + nf * 8 + grp;
            uint32_t b0 = B[(kl + qt) * PW + cb];
            uint32_t b1 = B[(kl + 4 + qt) * PW + cb];
            mma_tf32(acc[nf], a, b0, b1);
        }
    }
}

__global__ void __launch_bounds__(512, 1)
gene_mlp_kernel(const float* __restrict__ x,
                const float* __restrict__ W1, const float* __restrict__ b1,
                const float* __restrict__ W2, const float* __restrict__ b2,
                const float* __restrict__ W3, const float* __restrict__ b3,
                float* __restrict__ out) {
    extern __shared__ float sm[];
    float* shH  = sm + OFF_H;
    float* shW  = sm + OFF_W;
    float* shB1 = sm + OFF_B1;
    float* shB2 = sm + OFF_B2;
    float* shW3 = sm + OFF_W3;
    float* shO  = sm + OFF_O;

    const int g       = blockIdx.x >> 1;
    const int rowbase = (blockIdx.x & 1) * 64;
    const int tid  = threadIdx.x;
    const int lane = tid & 31;
    const int warp = tid >> 5;       // 0..15
    const int wm = warp & 3;         // 4 m-warps (16 rows each)
    const int wn = warp >> 2;        // 4 n-warps (64 cols each)
    const int grp = lane >> 2;
    const int qt  = lane & 3;

    // ---- stage biases / W3, zero output accumulator ----
    shB1[tid] = b1[(size_t)g * HID + tid];
    shB2[tid] = b2[(size_t)g * HID + tid];
    shW3[tid] = W3[(size_t)g * HID + tid];
    if (tid < 64) shO[tid] = 0.0f;

    const float* xg = x + (size_t)rowbase * LAT;

    // ================= Phase 1: h1 = gelu(x @ W1 + b1) -> shH (tf32) ============
    const float* W1g = W1 + (size_t)g * LAT * HID;
#pragma unroll 1
    for (int n1t = 0; n1t < 2; ++n1t) {
        const int n0 = n1t * 256;
        float acc[8][4];
#pragma unroll
        for (int nf = 0; nf < 8; ++nf)
#pragma unroll
            for (int i = 0; i < 4; ++i) acc[nf][i] = 0.0f;

        float4 pre[4];
        load_tile(pre, W1g, 0, n0, tid);
        store_tile(shW, pre, tid);                 // chunk 0 -> buf 0
        load_tile(pre, W1g, 32, n0, tid);          // chunk 1 -> regs
        __syncthreads();
#pragma unroll 1
        for (int kc = 0; kc < 4; ++kc) {
            if (kc + 1 < 4) store_tile(shW + ((kc + 1) & 1) * WCHUNK, pre, tid);
            if (kc + 2 < 4) load_tile(pre, W1g, (kc + 2) * 32, n0, tid);
            mma_chunk_gx(acc, xg, kc * 32, shW + (kc & 1) * WCHUNK, wm, wn, grp, qt);
            __syncthreads();
        }
        // epilogue: bias + gelu + tf32-store into shH
#pragma unroll
        for (int nf = 0; nf < 8; ++nf)
#pragma unroll
            for (int i = 0; i < 4; ++i) {
                int row  = wm * 16 + (i >> 1) * 8 + grp;
                int col  = n0 + wn * 64 + nf * 8 + 2 * qt + (i & 1);
                float v = acc[nf][i] + shB1[col];
                shH[row * PH + col] = to_tf32(gelu_exact(v));
            }
    }

    // ================= Phase 2: h2 = gelu(h1 @ W2 + b2); out += h2 . W3 =========
    const float* W2g = W2 + (size_t)g * HID * HID;
#pragma unroll 1
    for (int n2t = 0; n2t < 2; ++n2t) {
        const int n0 = n2t * 256;
        float acc[8][4];
#pragma unroll
        for (int nf = 0; nf < 8; ++nf)
#pragma unroll
            for (int i = 0; i < 4; ++i) acc[nf][i] = 0.0f;

        float4 pre[4];
        load_tile(pre, W2g, 0, n0, tid);
        store_tile(shW, pre, tid);
        load_tile(pre, W2g, 32, n0, tid);
        __syncthreads();                            // also orders phase-1 shH writes
#pragma unroll 1
        for (int kc = 0; kc < 16; ++kc) {
            if (kc + 1 < 16) store_tile(shW + ((kc + 1) & 1) * WCHUNK, pre, tid);
            if (kc + 2 < 16) load_tile(pre, W2g, (kc + 2) * 32, n0, tid);
            mma_chunk_sh(acc, shH, PH, kc * 32, shW + (kc & 1) * WCHUNK, wm, wn, grp, qt);
            __syncthreads();
        }
        // epilogue: bias + gelu + fused dot with W3 (fp32)
        float part[2] = {0.f, 0.f};
#pragma unroll
        for (int nf = 0; nf < 8; ++nf)
#pragma unroll
            for (int i = 0; i < 4; ++i) {
                int col = n0 + wn * 64 + nf * 8 + 2 * qt + (i & 1);
                float v = gelu_exact(acc[nf][i] + shB2[col]);
                part[i >> 1] += v * shW3[col];
            }
#pragma unroll
        for (int r = 0; r < 2; ++r) {
            part[r] += __shfl_xor_sync(0xffffffffu, part[r], 1);
            part[r] += __shfl_xor_sync(0xffffffffu, part[r], 2);
        }
        if (qt == 0) {
            atomicAdd(&shO[wm * 16 + grp],     part[0]);
            atomicAdd(&shO[wm * 16 + 8 + grp], part[1]);
        }
    }

    __syncthreads();
    if (tid < 64) {
        out[(size_t)(rowbase + tid) * GENES + g] = shO[tid] + b3[g];
    }
}

extern "C" void kernel_launch(void* const* d_in, const int* in_sizes, int n_in,
                              void* d_out, int out_size) {
    const float* x  = (const float*)d_in[0];
    const float* W1 = (const float*)d_in[1];
    const float* b1 = (const float*)d_in[2];
    const float* W2 = (const float*)d_in[3];
    const float* b2 = (const float*)d_in[4];
    const float* W3 = (const float*)d_in[5];
    const float* b3 = (const float*)d_in[6];
    float* out = (float*)d_out;

    cudaFuncSetAttribute(gene_mlp_kernel,
                         cudaFuncAttributeMaxDynamicSharedMemorySize, SMEM_BYTES);
    gene_mlp_kernel<<<2 * GENES, 512, SMEM_BYTES>>>(x, W1, b1, W2, b2, W3, b3, out);
}